// round 2
// baseline (speedup 1.0000x reference)
#include <cuda_runtime.h>
#include <cuda_bf16.h>

#define BH_ 64
#define KP_ 512
#define NN_ 4096
#define DD_ 64
#define KT_ 64
#define TN_ 64
#define SROW_ 68   // padded row stride (floats) for 128b-aligned vector LDS

__device__ float g_z[BH_ * NN_];

__device__ __forceinline__ void fma2(unsigned long long &c, unsigned long long a, unsigned long long b) {
    asm("fma.rn.f32x2 %0, %1, %2, %0;" : "+l"(c) : "l"(a), "l"(b));
}
__device__ __forceinline__ float2 up2(unsigned long long u) {
    float2 r; asm("mov.b64 {%0, %1}, %2;" : "=f"(r.x), "=f"(r.y) : "l"(u)); return r;
}
__device__ __forceinline__ unsigned long long pk2(float x, float y) {
    unsigned long long u; asm("mov.b64 %0, {%1, %2};" : "=l"(u) : "f"(x), "f"(y)); return u;
}

// ---------------------------------------------------------------------------
// Kernel 1: z[bh,n] = sum_k exp(K[bh,k,:] . xk[bh,n,:])
// grid (BH, NN/256), 256 threads; one column per thread, x held in registers
// (packed f32x2), K chunks staged in smem and broadcast.
// ---------------------------------------------------------------------------
__global__ __launch_bounds__(256) void hm_zk(const float* __restrict__ K,
                                             const float* __restrict__ xk) {
    int bh = blockIdx.x;
    int n  = blockIdx.y * 256 + threadIdx.x;
    const float* Kb = K  + (size_t)bh * KP_ * DD_;
    const float* xr = xk + (size_t)bh * NN_ * DD_ + (size_t)n * DD_;

    unsigned long long x2[32];
#pragma unroll
    for (int i = 0; i < 16; i++) {
        float4 v = ((const float4*)xr)[i];
        x2[2*i]   = pk2(v.x, v.y);
        x2[2*i+1] = pk2(v.z, v.w);
    }

    __shared__ float Ks[64 * 64];
    float z = 0.f;
    for (int kc = 0; kc < KP_; kc += 64) {
        __syncthreads();
#pragma unroll
        for (int i = 0; i < 4; i++)
            ((float4*)Ks)[threadIdx.x + i * 256] =
                ((const float4*)(Kb + kc * DD_))[threadIdx.x + i * 256];
        __syncthreads();
#pragma unroll 2
        for (int kk = 0; kk < 64; kk++) {
            unsigned long long s0 = 0ull, s1 = 0ull, s2 = 0ull, s3 = 0ull;
            const ulonglong2* kr = (const ulonglong2*)(Ks + kk * 64);
#pragma unroll
            for (int d4 = 0; d4 < 16; d4 += 2) {
                ulonglong2 kv0 = kr[d4];
                ulonglong2 kv1 = kr[d4 + 1];
                fma2(s0, kv0.x, x2[2*d4]);
                fma2(s1, kv0.y, x2[2*d4+1]);
                fma2(s2, kv1.x, x2[2*d4+2]);
                fma2(s3, kv1.y, x2[2*d4+3]);
            }
            float2 a = up2(s0), b = up2(s1), c = up2(s2), d = up2(s3);
            float dist = ((a.x + a.y) + (b.x + b.y)) + ((c.x + c.y) + (d.x + d.y));
            z += __expf(dist);
        }
    }
    g_z[(size_t)bh * NN_ + n] = z;
}

// ---------------------------------------------------------------------------
// Kernel 2: block = (bh, 64-row k-slice). Streams N in 64-col tiles:
//   GEMM-A: dists[64,64] = Kslice @ xk_tile^T   (register tiled 4k x 4n)
//   epilogue: w = exp(dist) * (1/z[n]) -> smem; S[k] partials in regs
//   GEMM-B: accK/accV[64,64] += w @ {xk,xv}_tile (register accum 4k x 4d, f32x2)
// Final: gK = accK/S - K, gV = accV/S - V written directly (block-exclusive).
// ---------------------------------------------------------------------------
__global__ __launch_bounds__(256) void hm_mk(const float* __restrict__ K,
                                             const float* __restrict__ V,
                                             const float* __restrict__ xk,
                                             const float* __restrict__ xv,
                                             float* __restrict__ out) {
    extern __shared__ float sm[];
    float* sK  = sm;                      // [KT_][SROW_]
    float* sxk = sK  + KT_ * SROW_;       // [TN_][SROW_]
    float* sxv = sxk + TN_ * SROW_;       // [TN_][SROW_]
    float* sw  = sxv + TN_ * SROW_;       // [KT_][SROW_]  (w, later aliased for S-reduce)
    float* szr = sw  + KT_ * SROW_;       // [TN_] reciprocal z
    float* sS  = szr + TN_;               // [KT_] reciprocal S

    int bh  = blockIdx.x;
    int k0  = blockIdx.y * KT_;
    int tid = threadIdx.x;
    int kt  = tid >> 4;     // 0..15 -> k rows [4kt, 4kt+4)
    int nt  = tid & 15;     // 0..15 -> n cols [4nt, 4nt+4) (GEMM-A) / d cols (GEMM-B)

    const float* Kb  = K  + (size_t)bh * KP_ * DD_ + (size_t)k0 * DD_;
    const float* Vb  = V  + (size_t)bh * KP_ * DD_ + (size_t)k0 * DD_;
    const float* xkb = xk + (size_t)bh * NN_ * DD_;
    const float* xvb = xv + (size_t)bh * NN_ * DD_;
    const float* zb  = g_z + (size_t)bh * NN_;

    // Load K slice (64x64) into padded smem, resident for the whole block.
#pragma unroll
    for (int t = 0; t < 4; t++) {
        int f = tid + t * 256;          // float4 index, 1024 total
        int r = f >> 4, c = f & 15;
        *(float4*)&sK[r * SROW_ + c * 4] = ((const float4*)Kb)[f];
    }

    unsigned long long aK[4][2], aV[4][2];
#pragma unroll
    for (int i = 0; i < 4; i++) { aK[i][0]=aK[i][1]=aV[i][0]=aV[i][1]=0ull; }
    float sloc[4] = {0.f, 0.f, 0.f, 0.f};

#pragma unroll 1
    for (int n0 = 0; n0 < NN_; n0 += TN_) {
        __syncthreads();   // previous tile's sxk/sxv/sw fully consumed
#pragma unroll
        for (int t = 0; t < 4; t++) {
            int f = tid + t * 256;
            int r = f >> 4, c = f & 15;
            *(float4*)&sxk[r * SROW_ + c * 4] = ((const float4*)(xkb + (size_t)n0 * DD_))[f];
            *(float4*)&sxv[r * SROW_ + c * 4] = ((const float4*)(xvb + (size_t)n0 * DD_))[f];
        }
        if (tid < TN_) szr[tid] = 1.0f / zb[n0 + tid];
        __syncthreads();

        // ---- GEMM-A: dists (4k x 4n per thread), packed along d ----
        unsigned long long c2[4][4];
#pragma unroll
        for (int i = 0; i < 4; i++)
#pragma unroll
            for (int j = 0; j < 4; j++) c2[i][j] = 0ull;

        const float* kbase = sK  + (4 * kt) * SROW_;
        const float* xbase = sxk + (4 * nt) * SROW_;
#pragma unroll 4
        for (int d = 0; d < DD_; d += 4) {
            ulonglong2 a[4], b[4];
#pragma unroll
            for (int i = 0; i < 4; i++) a[i] = *(const ulonglong2*)(kbase + i * SROW_ + d);
#pragma unroll
            for (int j = 0; j < 4; j++) b[j] = *(const ulonglong2*)(xbase + j * SROW_ + d);
#pragma unroll
            for (int i = 0; i < 4; i++)
#pragma unroll
                for (int j = 0; j < 4; j++) {
                    fma2(c2[i][j], a[i].x, b[j].x);
                    fma2(c2[i][j], a[i].y, b[j].y);
                }
        }

        // ---- epilogue: w = exp(dist) / z[n], write to sw, accumulate S ----
        float rz0 = szr[4*nt], rz1 = szr[4*nt+1], rz2 = szr[4*nt+2], rz3 = szr[4*nt+3];
#pragma unroll
        for (int i = 0; i < 4; i++) {
            float2 p0 = up2(c2[i][0]); float w0 = __expf(p0.x + p0.y) * rz0;
            float2 p1 = up2(c2[i][1]); float w1 = __expf(p1.x + p1.y) * rz1;
            float2 p2 = up2(c2[i][2]); float w2 = __expf(p2.x + p2.y) * rz2;
            float2 p3 = up2(c2[i][3]); float w3 = __expf(p3.x + p3.y) * rz3;
            sloc[i] += (w0 + w1) + (w2 + w3);
            *(float4*)&sw[(4 * kt + i) * SROW_ + 4 * nt] = make_float4(w0, w1, w2, w3);
        }
        __syncthreads();

        // ---- GEMM-B: accK/accV += w @ x, packed along d ----
        const float* wbase = sw  + (4 * kt) * SROW_;
        const float* xka   = sxk + 4 * nt;
        const float* xva   = sxv + 4 * nt;
#pragma unroll 2
        for (int n = 0; n < TN_; n += 4) {
            float4 wv[4];
#pragma unroll
            for (int i = 0; i < 4; i++) wv[i] = *(const float4*)(wbase + i * SROW_ + n);
#pragma unroll
            for (int q = 0; q < 4; q++) {
                ulonglong2 bk = *(const ulonglong2*)(xka + (n + q) * SROW_);
                ulonglong2 bv = *(const ulonglong2*)(xva + (n + q) * SROW_);
#pragma unroll
                for (int i = 0; i < 4; i++) {
                    float wq = (q == 0) ? wv[i].x : (q == 1) ? wv[i].y : (q == 2) ? wv[i].z : wv[i].w;
                    unsigned long long wd = pk2(wq, wq);
                    fma2(aK[i][0], wd, bk.x);
                    fma2(aK[i][1], wd, bk.y);
                    fma2(aV[i][0], wd, bv.x);
                    fma2(aV[i][1], wd, bv.y);
                }
            }
        }
    }

    // ---- S reduction across the 16 nt-groups (alias sw as [16][KT_]) ----
    __syncthreads();
    *(float4*)&sw[nt * KT_ + 4 * kt] = make_float4(sloc[0], sloc[1], sloc[2], sloc[3]);
    __syncthreads();
    if (tid < KT_) {
        float s = 0.f;
#pragma unroll
        for (int r = 0; r < 16; r++) s += sw[r * KT_ + tid];
        sS[tid] = 1.0f / s;
    }
    __syncthreads();

    // ---- finalize: gK = accK/S - K, gV = accV/S - V ----
    size_t obase = (size_t)bh * KP_ * DD_ + (size_t)k0 * DD_;
    float* outK = out + obase;
    float* outV = out + (size_t)BH_ * KP_ * DD_ + obase;
#pragma unroll
    for (int i = 0; i < 4; i++) {
        int kk = 4 * kt + i;
        float rs = sS[kk];
        float2 k01 = up2(aK[i][0]), k23 = up2(aK[i][1]);
        float2 v01 = up2(aV[i][0]), v23 = up2(aV[i][1]);
        int off = kk * DD_ + 4 * nt;
        float4 kv = *(const float4*)&Kb[off];
        float4 vv = *(const float4*)&Vb[off];
        *(float4*)&outK[off] = make_float4(k01.x * rs - kv.x, k01.y * rs - kv.y,
                                           k23.x * rs - kv.z, k23.y * rs - kv.w);
        *(float4*)&outV[off] = make_float4(v01.x * rs - vv.x, v01.y * rs - vv.y,
                                           v23.x * rs - vv.z, v23.y * rs - vv.w);
    }
}

extern "C" void kernel_launch(void* const* d_in, const int* in_sizes, int n_in,
                              void* d_out, int out_size) {
    (void)in_sizes; (void)n_in; (void)out_size;
    const float* K  = (const float*)d_in[0];
    const float* V  = (const float*)d_in[1];
    const float* xk = (const float*)d_in[2];
    const float* xv = (const float*)d_in[3];
    float* out = (float*)d_out;

    const int smem_bytes = (KT_ * SROW_ + 2 * TN_ * SROW_ + KT_ * SROW_ + TN_ + KT_) * 4;
    cudaFuncSetAttribute(hm_mk, cudaFuncAttributeMaxDynamicSharedMemorySize, smem_bytes);

    hm_zk<<<dim3(BH_, NN_ / 256), 256>>>(K, xk);
    hm_mk<<<dim3(BH_, KP_ / KT_), 256, smem_bytes>>>(K, V, xk, xv, out);
}